// round 3
// baseline (speedup 1.0000x reference)
#include <cuda_runtime.h>
#include <cuda_bf16.h>

#define RECAL 0.9162907600402832f

// Bit-exact replica of XLA CPU's inline vectorized expf (llvm_ir_runtime
// GenerateVF32Exp, the Cephes/Eigen pexp expansion). On aarch64 the
// llvm.fmuladd calls lower to fused FMA -> __fmaf_rn here; the Cody-Waite
// range-reduction steps are explicit Mul/Sub (NOT fused) -> __fmul_rn/__fsub_rn.
__device__ __forceinline__ float xla_cpu_expf(float x)
{
    x = fminf(fmaxf(x, -88.3762626647949f), 88.3762626647950f);

    float fx = floorf(__fmaf_rn(x, 1.44269504088896341f, 0.5f));

    float tmp = __fmul_rn(0.693359375f, fx);
    float z   = __fmul_rn(-2.12194440e-4f, fx);
    float xr  = __fsub_rn(x, tmp);
    xr        = __fsub_rn(xr, z);

    float z2 = __fmul_rn(xr, xr);

    float y = __fmaf_rn(xr, 1.9875691500E-4f, 1.3981999507E-3f);
    y = __fmaf_rn(y, xr, 8.3334519073E-3f);
    y = __fmaf_rn(y, xr, 4.1665795894E-2f);
    y = __fmaf_rn(y, xr, 1.6666665459E-1f);
    y = __fmaf_rn(y, xr, 5.0000001201E-1f);
    y = __fmaf_rn(y, z2, xr);
    y = __fadd_rn(1.0f, y);

    // fx is integral and clamped; FPToSI is exact truncation.
    int emm0 = (int)fx;
    float scale = __int_as_float((emm0 + 127) << 23);

    return fmaxf(__fmul_rn(y, scale), x);
}

// logistic(t) = 1 / (1 + exp(-t))  -- XLA LogisticExpander form, f32 ops.
__device__ __forceinline__ float xla_logistic(float t)
{
    float e = xla_cpu_expf(-t);
    return __fdiv_rn(1.0f, __fadd_rn(1.0f, e));
}

__global__ __launch_bounds__(256) void hbc_kernel(
    const float* __restrict__ logit,
    const float* __restrict__ bin_pos,
    const float* __restrict__ bin_ex,
    const float* __restrict__ boundaries,
    const int*   __restrict__ seg_val,
    const int*   __restrict__ seg_len,
    float*       __restrict__ out,
    int n, int num_bins, int num_segments)
{
    int i4 = (blockIdx.x * blockDim.x + threadIdx.x) * 4;
    if (i4 >= n) return;

    float lg[4];
    int   sv[4], sl[4];

    if (i4 + 3 < n) {
        float4 l = *reinterpret_cast<const float4*>(logit + i4);
        int4   v = *reinterpret_cast<const int4*>(seg_val + i4);
        int4   s = *reinterpret_cast<const int4*>(seg_len + i4);
        lg[0]=l.x; lg[1]=l.y; lg[2]=l.z; lg[3]=l.w;
        sv[0]=v.x; sv[1]=v.y; sv[2]=v.z; sv[3]=v.w;
        sl[0]=s.x; sl[1]=s.y; sl[2]=s.z; sl[3]=s.w;
    } else {
        #pragma unroll
        for (int k = 0; k < 4; k++) {
            int i = i4 + k;
            lg[k] = (i < n) ? logit[i] : 0.0f;
            sv[k] = (i < n) ? seg_val[i] : 0;
            sl[k] = (i < n) ? seg_len[i] : 1;
        }
    }

    float orig[4];
    int   idx[4];

    #pragma unroll
    for (int k = 0; k < 4; k++) {
        float t = __fadd_rn(lg[k], -RECAL);  // logit - RECAL, single f32 rounding
        float o = xla_logistic(t);
        orig[k] = o;

        // segment id: cumsum(ones)-scatter degenerates to identity; len==1 gate; clamp
        int seg = (sl[k] == 1) ? (sv[k] + 1) : 0;
        if (seg > num_segments || seg < 0) seg = 0;

        // searchsorted(boundaries, o, side='left'): analytic guess on the uniform
        // grid + exact correction against the true f32 boundary values.
        int g = (int)(o * (float)num_bins);
        if (g < 0) g = 0;
        if (g > num_bins - 1) g = num_bins - 1;
        while (g > 0 && __ldg(&boundaries[g - 1]) >= o) --g;
        while (g < num_bins - 1 && __ldg(&boundaries[g]) < o) ++g;

        idx[k] = g + seg * num_bins;
    }

    // issue all 8 gathers before consuming (MLP hides L2 latency)
    float pos[4], ex[4];
    #pragma unroll
    for (int k = 0; k < 4; k++) pos[k] = __ldg(&bin_pos[idx[k]]);
    #pragma unroll
    for (int k = 0; k < 4; k++) ex[k]  = __ldg(&bin_ex[idx[k]]);

    float res[4];
    #pragma unroll
    for (int k = 0; k < 4; k++) {
        float calibrated = __fadd_rn(__fmul_rn(__fdiv_rn(pos[k], ex[k]), 0.9995f),
                                     __fmul_rn(orig[k], 0.0005f));
        res[k] = (ex[k] > 10000.0f) ? calibrated : orig[k];
    }

    if (i4 + 3 < n) {
        *reinterpret_cast<float4*>(out + i4) = make_float4(res[0], res[1], res[2], res[3]);
    } else {
        for (int k = 0; k < 4 && i4 + k < n; k++) out[i4 + k] = res[k];
    }
}

extern "C" void kernel_launch(void* const* d_in, const int* in_sizes, int n_in,
                              void* d_out, int out_size)
{
    const float* logit      = (const float*)d_in[0];
    const float* bin_pos    = (const float*)d_in[1];
    const float* bin_ex     = (const float*)d_in[2];
    const float* boundaries = (const float*)d_in[3];
    const int*   seg_val    = (const int*)d_in[4];
    const int*   seg_len    = (const int*)d_in[5];
    float*       out        = (float*)d_out;

    int n = in_sizes[0];                    // logit element count (N*1)
    int num_bins = in_sizes[3] + 1;         // boundaries has num_bins-1 entries
    int num_segments = in_sizes[1] / num_bins - 1;

    int elems_per_block = 256 * 4;
    int grid = (n + elems_per_block - 1) / elems_per_block;
    hbc_kernel<<<grid, 256>>>(logit, bin_pos, bin_ex, boundaries,
                              seg_val, seg_len, out, n, num_bins, num_segments);
}